// round 13
// baseline (speedup 1.0000x reference)
#include <cuda_runtime.h>

// Problem constants (fixed by the reference).
#define NB 4096      // bodies
#define KB 16384     // broad-phase keep count
#define KE 4096      // exact-phase keep count

// Spatial grid: rsum <= 3.0 (radii in [0.5,1.5]); cell 3.25 guarantees any
// AABB-overlapping pair sits in adjacent cells, incl. under edge clamping.
#define NC 128
#define NCELLS (NC * NC)
#define CELL 3.25f
#define ORG  (-208.0f)
#define CAPC 32        // bucket capacity per cell (peak occupancy ~ Poisson(4.4))
#define CAP  64        // per-row gathered list cap (fallback: warp brute scan)
#define FULLM 0xffffffffu

#define NBLKS 128      // 1 block/SM => co-resident; 4096 warps = 1 warp/body
#define TPB   1024
#define NGRP  8        // two-level barrier: 8 groups x 16 blocks

// ---- device scratch (no allocations; all state self-restoring across replays) ----
__device__ int    g_cellCnt[NCELLS];          // zero-init; re-zeroed in P4
__device__ float4 g_bucket[NCELLS * CAPC];    // (x, y, r, bitcast(idx))
__device__ int2   g_blkSum[NBLKS];            // per-block (sumA, sumP)
__device__ int    g_winner[NB];               // 0=none; restored by atomicExch in P4
__device__ float  g_evx[KE];
__device__ float  g_evy[KE];

// two-level monotone barrier state (never reset => replay-safe):
// release spin on ONE L2 line (cheap broadcast), arrivals fan over 8 lines.
__device__ int g_grp[NGRP * 32];              // stride 32 ints (no false sharing)
__device__ int g_root;
__device__ int g_gen;

__device__ __forceinline__ void gsync() {
    __syncthreads();
    if (threadIdx.x == 0) {
        int my = *(volatile int*)&g_gen;        // read BEFORE arriving
        __threadfence();
        int v = atomicAdd(&g_grp[(blockIdx.x & (NGRP - 1)) * 32], 1) + 1;
        if ((v & 15) == 0) {                    // 16 blocks per group
            int r = atomicAdd(&g_root, 1) + 1;
            if ((r & (NGRP - 1)) == 0) {
                __threadfence();
                atomicAdd(&g_gen, 1);
            }
        }
        while (*(volatile int*)&g_gen == my) { }
        __threadfence();
    }
    __syncthreads();
}

// Pinned-rounding pair predicate — bit-identical at every use site.
__device__ __forceinline__ void pair_flags(float xi, float yi, float ri,
                                           float xj, float yj, float rj,
                                           bool self, bool& A, bool& P) {
    float dx = fabsf(__fsub_rn(xi, xj));
    float dy = fabsf(__fsub_rn(yi, yj));
    float rs = __fadd_rn(ri, rj);
    A = (dx <= rs) & (dy <= rs) & (!self);
    float d2 = __fadd_rn(__fmaf_rn(dy, dy, __fmul_rn(dx, dx)), 1e-12f);
    P = A & (d2 < __fmul_rn(rs, rs));   // pen>0 <=> rs^2 > d^2+eps (monotone)
}

__device__ __forceinline__ void emit_pair(int slot, int i, int j,
                                          float xi, float yi, float ri,
                                          float xj, float yj, float rj) {
    float dvx = __fsub_rn(xi, xj);
    float dvy = __fsub_rn(yi, yj);
    float rs  = __fadd_rn(ri, rj);
    float d2  = __fadd_rn(__fmaf_rn(dvy, dvy, __fmul_rn(dvx, dvx)), 1e-12f);
    float dist = __fsqrt_rn(d2);
    float s = __fdiv_rn(__fsub_rn(rs, dist), dist);     // pen_depth / dist
    g_evx[slot] = __fmul_rn(dvx, s);
    g_evy[slot] = __fmul_rn(dvy, s);
    atomicMax(&g_winner[i], slot + 1);        // i-phase
    atomicMax(&g_winner[j], slot + 1 + KE);   // j-phase (applied after all i's)
}

// Block-wide exclusive scan over 1024 ints (only the rare partial-row path).
__device__ __forceinline__ int scan1024(int v, int* sh32, int t) {
    int lane = t & 31, w = t >> 5;
    int x = v;
    #pragma unroll
    for (int d = 1; d < 32; d <<= 1) {
        int y = __shfl_up_sync(FULLM, x, d);
        if (lane >= d) x += y;
    }
    if (lane == 31) sh32[w] = x;
    __syncthreads();
    if (w == 0) {
        int s = sh32[lane];
        int acc = s;
        #pragma unroll
        for (int d = 1; d < 32; d <<= 1) {
            int y = __shfl_up_sync(FULLM, acc, d);
            if (lane >= d) acc += y;
        }
        sh32[lane] = acc - s;
    }
    __syncthreads();
    int r = sh32[w] + x - v;
    __syncthreads();
    return r;
}

// warp-collective neighbor candidate setup: 9 cells around (cx,cy).
__device__ __forceinline__ int nei_setup(int cx, int cy, int lane,
                                         int* st, int* ct, int* ce) {
    int mycell = -1, mycnt = 0;
    if (lane < 9) {
        int x = cx + (lane % 3) - 1;
        int y = cy + (lane / 3) - 1;
        if (x >= 0 && x < NC && y >= 0 && y < NC) {
            mycell = y * NC + x;
            mycnt = min(g_cellCnt[mycell], CAPC);
        }
    }
    int inc = mycnt;
    #pragma unroll
    for (int d = 1; d < 16; d <<= 1) {
        int y = __shfl_up_sync(FULLM, inc, d);
        if (lane >= d) inc += y;
    }
    int total = __shfl_sync(FULLM, inc, 8);
    int myst = inc - mycnt;
    #pragma unroll
    for (int k = 0; k < 9; k++) {
        st[k] = __shfl_sync(FULLM, myst, k);
        ct[k] = __shfl_sync(FULLM, mycnt, k);
        ce[k] = __shfl_sync(FULLM, mycell, k);
    }
    return total;
}
__device__ __forceinline__ int cand_addr(const int* st, const int* ct,
                                         const int* ce, int c) {
    int bcell = 0, boff = 0;
    #pragma unroll
    for (int k = 0; k < 9; k++)
        if (c >= st[k] && c < st[k] + ct[k]) { bcell = ce[k]; boff = c - st[k]; }
    return bcell * CAPC + boff;
}

__global__ void __launch_bounds__(TPB, 1)
k_all(const float* __restrict__ pos, const float* __restrict__ rad,
      float* __restrict__ out) {
    __shared__ int sh32[32];
    __shared__ int shCA[32], shCP[32];          // per-warp row counts
    __shared__ int shAllowed[32], shPrefE[32];
    __shared__ int shProw, shAllowedP, shPrefP;
    __shared__ int sPA[NBLKS], sPP[NBLKS];      // exclusive block prefixes
    __shared__ int jls[32][CAP];                // 8 KB: per-warp P-hit j-lists

    int t    = threadIdx.x;
    int blk  = blockIdx.x;
    int lane = t & 31;
    int wib  = t >> 5;
    int i    = blk * 32 + wib;                  // body owned by this warp
    const float2* p2 = (const float2*)pos;

    // ---- P0: warp-leader inserts own body into its cell bucket ----
    float xi, yi, ri;
    int cellc;
    {
        float px = 0.f, py = 0.f, pr = 0.f;
        int c = 0;
        if (lane == 0) {
            float2 p = p2[i];
            px = p.x; py = p.y; pr = rad[i];
            int cx = (int)floorf((px - ORG) / CELL);
            int cy = (int)floorf((py - ORG) / CELL);
            cx = min(max(cx, 0), NC - 1);
            cy = min(max(cy, 0), NC - 1);
            c = cy * NC + cx;
            int idx = atomicAdd(&g_cellCnt[c], 1);
            if (idx < CAPC)
                g_bucket[c * CAPC + idx] =
                    make_float4(px, py, pr, __int_as_float(i));
        }
        xi    = __shfl_sync(FULLM, px, 0);
        yi    = __shfl_sync(FULLM, py, 0);
        ri    = __shfl_sync(FULLM, pr, 0);
        cellc = __shfl_sync(FULLM, c, 0);
    }
    if (t == 0) { shProw = -1; shAllowedP = 0; }
    gsync();

    // ---- P1: warp-per-body A/P counts + gather P-hit j-list into smem ----
    int cp;                                     // P count (uniform in warp)
    {
        int cx = cellc & (NC - 1), cy = cellc >> 7;
        int st[9], ct[9], ce[9];
        int total = nei_setup(cx, cy, lane, st, ct, ce);
        int ca = 0, k = 0;
        for (int base = 0; base < total; base += 32) {
            int c = base + lane;
            bool A = false, P = false;
            int j = -1;
            if (c < total) {
                float4 b = g_bucket[cand_addr(st, ct, ce, c)];
                j = __float_as_int(b.w);
                pair_flags(xi, yi, ri, b.x, b.y, b.z, j == i, A, P);
            }
            ca += __popc(__ballot_sync(FULLM, A));
            unsigned bp = __ballot_sync(FULLM, P);
            if (P) {
                int slot = k + __popc(bp & ((1u << lane) - 1u));
                if (slot < CAP) jls[wib][slot] = j;
            }
            k += __popc(bp);
        }
        cp = k;
        if (lane == 0) { shCA[wib] = ca; shCP[wib] = cp; }
    }
    __syncthreads();
    if (wib == 0) {                             // publish block sums
        int sa = __reduce_add_sync(FULLM, shCA[lane]);
        int sp = __reduce_add_sync(FULLM, shCP[lane]);
        if (lane == 0) g_blkSum[blk] = make_int2(sa, sp);
    }
    gsync();

    // ---- P2: hierarchical prefix (128 block sums) + cutoff ----
    if (wib == 0) {                             // scan 128 block sums
        int2 v0 = g_blkSum[4 * lane + 0];
        int2 v1 = g_blkSum[4 * lane + 1];
        int2 v2 = g_blkSum[4 * lane + 2];
        int2 v3 = g_blkSum[4 * lane + 3];
        int gA = v0.x + v1.x + v2.x + v3.x;
        int gP = v0.y + v1.y + v2.y + v3.y;
        int xA = gA, xP = gP;
        #pragma unroll
        for (int d = 1; d < 32; d <<= 1) {
            int yA = __shfl_up_sync(FULLM, xA, d);
            int yP = __shfl_up_sync(FULLM, xP, d);
            if (lane >= d) { xA += yA; xP += yP; }
        }
        int baseAex = xA - gA, basePex = xP - gP;
        sPA[4 * lane + 0] = baseAex;
        sPA[4 * lane + 1] = baseAex + v0.x;
        sPA[4 * lane + 2] = baseAex + v0.x + v1.x;
        sPA[4 * lane + 3] = baseAex + v0.x + v1.x + v2.x;
        sPP[4 * lane + 0] = basePex;
        sPP[4 * lane + 1] = basePex + v0.y;
        sPP[4 * lane + 2] = basePex + v0.y + v1.y;
        sPP[4 * lane + 3] = basePex + v0.y + v1.y + v2.y;
    }
    __syncthreads();
    if (wib == 0) {                             // intra-block row prefixes
        int prefA0 = sPA[blk], prefP0 = sPP[blk];
        int ca = shCA[lane], cprow = shCP[lane];
        int xA = ca, xP = cprow;
        #pragma unroll
        for (int d = 1; d < 32; d <<= 1) {
            int yA = __shfl_up_sync(FULLM, xA, d);
            int yP = __shfl_up_sync(FULLM, xP, d);
            if (lane >= d) { xA += yA; xP += yP; }
        }
        int pref  = prefA0 + xA - ca;           // global exclusive A-prefix
        int prefE = prefP0 + xP - cprow;        // global exclusive P-prefix
        int a = KB - pref;
        if (a < 0) a = 0;
        if (a > ca) a = ca;
        shAllowed[lane] = a;
        shPrefE[lane]   = prefE;
        if (pref < KB && pref + ca > KB) {      // partial row lives in MY block
            shProw = blk * 32 + lane;
            shAllowedP = a;
            shPrefP = prefE;
        }
    }
    __syncthreads();

    // rare: this block owns the broad-cutoff partial row -> ordered brute emit
    if (shProw >= 0) {                          // block-uniform branch
        int prow = shProw;
        int allowedP = shAllowedP;
        float2 pp = p2[prow];
        float rp = rad[prow];
        unsigned mA = 0, mP = 0;
        int r0 = t * 4;
        #pragma unroll
        for (int m = 0; m < 4; m++) {
            int j = r0 + m;
            float2 pj = p2[j];
            bool A; bool P;
            pair_flags(pp.x, pp.y, rp, pj.x, pj.y, rad[j], j == prow, A, P);
            mA |= (unsigned)A << m;
            mP |= (unsigned)P << m;
        }
        int baseA = scan1024(__popc(mA), sh32, t);
        unsigned mC = 0;
        #pragma unroll
        for (int m = 0; m < 4; m++) {
            if ((mP >> m) & 1u) {
                int ar = baseA + __popc(mA & ((1u << m) - 1u));
                if (ar < allowedP) mC |= 1u << m;
            }
        }
        int slotBase = shPrefP + scan1024(__popc(mC), sh32, t);
        unsigned mm = mC;
        while (mm) {
            int m = __ffs(mm) - 1;
            mm &= mm - 1;
            int slot = slotBase++;
            if (slot < KE) {
                int j = r0 + m;
                float2 pj = p2[j];
                emit_pair(slot, prow, j, pp.x, pp.y, rp, pj.x, pj.y, rad[j]);
            }
        }
    }

    // ---- P3: warp-parallel RANK-based emit (replaces lane-0 insertion sort;
    //      within-row order = ascending j, so slot = baseE + #{b : j_b < j_a}) --
    {
        int prow = shProw;
        int allowed = shAllowed[wib];
        int baseE = shPrefE[wib];
        bool active = (i != prow) && (allowed != 0) && (baseE < KE) && (cp != 0);
        if (active) {
            // non-partial row with allowed > 0  =>  all P-hits kept
            if (cp <= CAP) {
                for (int a = lane; a < cp; a += 32) {
                    int ja = jls[wib][a];
                    int rank = 0;
                    for (int b = 0; b < cp; b++)
                        rank += (jls[wib][b] < ja);     // broadcast LDS reads
                    int slot = baseE + rank;
                    if (slot < KE) {
                        float xj = pos[2 * ja], yj = pos[2 * ja + 1];
                        emit_pair(slot, i, ja, xi, yi, ri, xj, yj, rad[ja]);
                    }
                }
            } else {
                // rare overflow: warp-strided ordered brute scan
                int rank = 0;
                for (int j0 = 0; j0 < NB; j0 += 32) {
                    int j = j0 + lane;
                    float xj = pos[2 * j], yj = pos[2 * j + 1], rj = rad[j];
                    bool A; bool P;
                    pair_flags(xi, yi, ri, xj, yj, rj, j == i, A, P);
                    unsigned bp = __ballot_sync(FULLM, P);
                    if (P) {
                        int slot = baseE + rank + __popc(bp & ((1u << lane) - 1u));
                        if (slot < KE)
                            emit_pair(slot, i, j, xi, yi, ri, xj, yj, rj);
                    }
                    rank += __popc(bp);
                }
            }
        }
    }
    gsync();

    // ---- P4: re-zero cell histogram + warp-leader resolve ----
    if (t < NCELLS / NBLKS) g_cellCnt[blk * (NCELLS / NBLKS) + t] = 0;
    if (lane == 0) {
        float x = xi, y = yi;
        int w = atomicExch(&g_winner[i], 0);    // read + restore in one op
        if (w > KE) {                            // j-write wins
            int k = w - KE - 1;
            x = __fsub_rn(x, __fmul_rn(0.5f, g_evx[k]));
            y = __fsub_rn(y, __fmul_rn(0.5f, g_evy[k]));
        } else if (w > 0) {                      // i-write wins
            int k = w - 1;
            x = __fadd_rn(x, __fmul_rn(0.5f, g_evx[k]));
            y = __fadd_rn(y, __fmul_rn(0.5f, g_evy[k]));
        }
        out[2 * i]     = x;
        out[2 * i + 1] = y;
    }
}

extern "C" void kernel_launch(void* const* d_in, const int* in_sizes, int n_in,
                              void* d_out, int out_size) {
    const float* pos;
    const float* rad;
    if (in_sizes[0] == 2 * NB) { pos = (const float*)d_in[0]; rad = (const float*)d_in[1]; }
    else                       { pos = (const float*)d_in[1]; rad = (const float*)d_in[0]; }
    float* out = (float*)d_out;

    k_all<<<NBLKS, TPB>>>(pos, rad, out);
}

// round 14
// speedup vs baseline: 1.0970x; 1.0970x over previous
#include <cuda_runtime.h>

// Problem constants (fixed by the reference).
#define NB 4096      // bodies
#define KB 16384     // broad-phase keep count
#define KE 4096      // exact-phase keep count

// Spatial grid: rsum <= 3.0 (radii in [0.5,1.5]); cell 3.25 guarantees any
// AABB-overlapping pair sits in adjacent cells, incl. under edge clamping.
#define NC 128
#define NCELLS (NC * NC)
#define CELL 3.25f
#define ORG  (-208.0f)
#define CAPC 32        // bucket capacity per cell (peak occupancy ~ Poisson(4.4))
#define CAP  64        // per-row gathered list cap (fallback: warp brute scan)
#define FULLM 0xffffffffu

#define NBLKS 128      // 1 block/SM => co-resident; 4096 warps = 1 warp/body
#define TPB   1024
#define NGRP  8        // two-level barrier: 8 groups x 16 blocks

// ---- device scratch (no allocations; all state self-restoring across replays) ----
__device__ int    g_cellCnt[NCELLS];          // zero-init; re-zeroed in P4
__device__ float4 g_bucket[NCELLS * CAPC];    // (x, y, r, bitcast(idx))
__device__ int2   g_blkSum[NBLKS];            // per-block (sumA, sumP)
__device__ int    g_winner[NB];               // 0=none; restored by atomicExch in P4
__device__ float  g_evx[KE];
__device__ float  g_evy[KE];

// two-level monotone barrier state (never reset => replay-safe):
// release spin on ONE L2 line (cheap broadcast), arrivals fan over 8 lines.
__device__ int g_grp[NGRP * 32];              // stride 32 ints (no false sharing)
__device__ int g_root;
__device__ int g_gen;

__device__ __forceinline__ void gsync() {
    __syncthreads();
    if (threadIdx.x == 0) {
        int my = *(volatile int*)&g_gen;        // read BEFORE arriving
        __threadfence();
        int v = atomicAdd(&g_grp[(blockIdx.x & (NGRP - 1)) * 32], 1) + 1;
        if ((v & 15) == 0) {                    // 16 blocks per group
            int r = atomicAdd(&g_root, 1) + 1;
            if ((r & (NGRP - 1)) == 0) {
                __threadfence();
                atomicAdd(&g_gen, 1);
            }
        }
        while (*(volatile int*)&g_gen == my) { }
        __threadfence();
    }
    __syncthreads();
}

// Pinned-rounding pair predicate — bit-identical at every use site.
__device__ __forceinline__ void pair_flags(float xi, float yi, float ri,
                                           float xj, float yj, float rj,
                                           bool self, bool& A, bool& P) {
    float dx = fabsf(__fsub_rn(xi, xj));
    float dy = fabsf(__fsub_rn(yi, yj));
    float rs = __fadd_rn(ri, rj);
    A = (dx <= rs) & (dy <= rs) & (!self);
    float d2 = __fadd_rn(__fmaf_rn(dy, dy, __fmul_rn(dx, dx)), 1e-12f);
    P = A & (d2 < __fmul_rn(rs, rs));   // pen>0 <=> rs^2 > d^2+eps (monotone)
}

__device__ __forceinline__ void emit_pair(int slot, int i, int j,
                                          float xi, float yi, float ri,
                                          float xj, float yj, float rj) {
    float dvx = __fsub_rn(xi, xj);
    float dvy = __fsub_rn(yi, yj);
    float rs  = __fadd_rn(ri, rj);
    float d2  = __fadd_rn(__fmaf_rn(dvy, dvy, __fmul_rn(dvx, dvx)), 1e-12f);
    float dist = __fsqrt_rn(d2);
    float s = __fdiv_rn(__fsub_rn(rs, dist), dist);     // pen_depth / dist
    g_evx[slot] = __fmul_rn(dvx, s);
    g_evy[slot] = __fmul_rn(dvy, s);
    atomicMax(&g_winner[i], slot + 1);        // i-phase
    atomicMax(&g_winner[j], slot + 1 + KE);   // j-phase (applied after all i's)
}

// Block-wide exclusive scan over 1024 ints (only the rare partial-row path).
__device__ __forceinline__ int scan1024(int v, int* sh32, int t) {
    int lane = t & 31, w = t >> 5;
    int x = v;
    #pragma unroll
    for (int d = 1; d < 32; d <<= 1) {
        int y = __shfl_up_sync(FULLM, x, d);
        if (lane >= d) x += y;
    }
    if (lane == 31) sh32[w] = x;
    __syncthreads();
    if (w == 0) {
        int s = sh32[lane];
        int acc = s;
        #pragma unroll
        for (int d = 1; d < 32; d <<= 1) {
            int y = __shfl_up_sync(FULLM, acc, d);
            if (lane >= d) acc += y;
        }
        sh32[lane] = acc - s;
    }
    __syncthreads();
    int r = sh32[w] + x - v;
    __syncthreads();
    return r;
}

// warp-collective neighbor candidate setup: 9 cells around (cx,cy).
__device__ __forceinline__ int nei_setup(int cx, int cy, int lane,
                                         int* st, int* ct, int* ce) {
    int mycell = -1, mycnt = 0;
    if (lane < 9) {
        int x = cx + (lane % 3) - 1;
        int y = cy + (lane / 3) - 1;
        if (x >= 0 && x < NC && y >= 0 && y < NC) {
            mycell = y * NC + x;
            mycnt = min(g_cellCnt[mycell], CAPC);
        }
    }
    int inc = mycnt;
    #pragma unroll
    for (int d = 1; d < 16; d <<= 1) {
        int y = __shfl_up_sync(FULLM, inc, d);
        if (lane >= d) inc += y;
    }
    int total = __shfl_sync(FULLM, inc, 8);
    int myst = inc - mycnt;
    #pragma unroll
    for (int k = 0; k < 9; k++) {
        st[k] = __shfl_sync(FULLM, myst, k);
        ct[k] = __shfl_sync(FULLM, mycnt, k);
        ce[k] = __shfl_sync(FULLM, mycell, k);
    }
    return total;
}
__device__ __forceinline__ int cand_addr(const int* st, const int* ct,
                                         const int* ce, int c) {
    int bcell = 0, boff = 0;
    #pragma unroll
    for (int k = 0; k < 9; k++)
        if (c >= st[k] && c < st[k] + ct[k]) { bcell = ce[k]; boff = c - st[k]; }
    return bcell * CAPC + boff;
}

__global__ void __launch_bounds__(TPB, 1)
k_all(const float* __restrict__ pos, const float* __restrict__ rad,
      float* __restrict__ out) {
    __shared__ int sh32[32];
    __shared__ int shCA[32], shCP[32];          // per-warp row counts
    __shared__ int shAllowed[32], shPrefE[32];
    __shared__ int shProw, shAllowedP, shPrefP;
    __shared__ int sPA[NBLKS], sPP[NBLKS];      // exclusive block prefixes
    __shared__ int jls[32][CAP];                // 8 KB: per-warp P-hit j-lists

    int t    = threadIdx.x;
    int blk  = blockIdx.x;
    int lane = t & 31;
    int wib  = t >> 5;
    int i    = blk * 32 + wib;                  // body owned by this warp
    const float2* p2 = (const float2*)pos;

    // ---- P0: warp-leader inserts own body into its cell bucket ----
    float xi, yi, ri;
    int cellc;
    {
        float px = 0.f, py = 0.f, pr = 0.f;
        int c = 0;
        if (lane == 0) {
            float2 p = p2[i];
            px = p.x; py = p.y; pr = rad[i];
            int cx = (int)floorf((px - ORG) / CELL);
            int cy = (int)floorf((py - ORG) / CELL);
            cx = min(max(cx, 0), NC - 1);
            cy = min(max(cy, 0), NC - 1);
            c = cy * NC + cx;
            int idx = atomicAdd(&g_cellCnt[c], 1);
            if (idx < CAPC)
                g_bucket[c * CAPC + idx] =
                    make_float4(px, py, pr, __int_as_float(i));
        }
        xi    = __shfl_sync(FULLM, px, 0);
        yi    = __shfl_sync(FULLM, py, 0);
        ri    = __shfl_sync(FULLM, pr, 0);
        cellc = __shfl_sync(FULLM, c, 0);
    }
    if (t == 0) { shProw = -1; shAllowedP = 0; }
    gsync();

    // ---- P1: warp-per-body A/P counts + gather P-hit j-list into smem ----
    int cp;                                     // P count (uniform in warp)
    {
        int cx = cellc & (NC - 1), cy = cellc >> 7;
        int st[9], ct[9], ce[9];
        int total = nei_setup(cx, cy, lane, st, ct, ce);
        int ca = 0, k = 0;
        for (int base = 0; base < total; base += 32) {
            int c = base + lane;
            bool A = false, P = false;
            int j = -1;
            if (c < total) {
                float4 b = g_bucket[cand_addr(st, ct, ce, c)];
                j = __float_as_int(b.w);
                pair_flags(xi, yi, ri, b.x, b.y, b.z, j == i, A, P);
            }
            ca += __popc(__ballot_sync(FULLM, A));
            unsigned bp = __ballot_sync(FULLM, P);
            if (P) {
                int slot = k + __popc(bp & ((1u << lane) - 1u));
                if (slot < CAP) jls[wib][slot] = j;
            }
            k += __popc(bp);
        }
        cp = k;
        if (lane == 0) { shCA[wib] = ca; shCP[wib] = cp; }
    }
    __syncthreads();
    if (wib == 0) {                             // publish block sums
        int sa = __reduce_add_sync(FULLM, shCA[lane]);
        int sp = __reduce_add_sync(FULLM, shCP[lane]);
        if (lane == 0) g_blkSum[blk] = make_int2(sa, sp);
    }
    gsync();

    // ---- P2: hierarchical prefix (128 block sums) + cutoff ----
    if (wib == 0) {                             // scan 128 block sums
        int2 v0 = g_blkSum[4 * lane + 0];
        int2 v1 = g_blkSum[4 * lane + 1];
        int2 v2 = g_blkSum[4 * lane + 2];
        int2 v3 = g_blkSum[4 * lane + 3];
        int gA = v0.x + v1.x + v2.x + v3.x;
        int gP = v0.y + v1.y + v2.y + v3.y;
        int xA = gA, xP = gP;
        #pragma unroll
        for (int d = 1; d < 32; d <<= 1) {
            int yA = __shfl_up_sync(FULLM, xA, d);
            int yP = __shfl_up_sync(FULLM, xP, d);
            if (lane >= d) { xA += yA; xP += yP; }
        }
        int baseAex = xA - gA, basePex = xP - gP;
        sPA[4 * lane + 0] = baseAex;
        sPA[4 * lane + 1] = baseAex + v0.x;
        sPA[4 * lane + 2] = baseAex + v0.x + v1.x;
        sPA[4 * lane + 3] = baseAex + v0.x + v1.x + v2.x;
        sPP[4 * lane + 0] = basePex;
        sPP[4 * lane + 1] = basePex + v0.y;
        sPP[4 * lane + 2] = basePex + v0.y + v1.y;
        sPP[4 * lane + 3] = basePex + v0.y + v1.y + v2.y;
    }
    __syncthreads();
    if (wib == 0) {                             // intra-block row prefixes
        int prefA0 = sPA[blk], prefP0 = sPP[blk];
        int ca = shCA[lane], cprow = shCP[lane];
        int xA = ca, xP = cprow;
        #pragma unroll
        for (int d = 1; d < 32; d <<= 1) {
            int yA = __shfl_up_sync(FULLM, xA, d);
            int yP = __shfl_up_sync(FULLM, xP, d);
            if (lane >= d) { xA += yA; xP += yP; }
        }
        int pref  = prefA0 + xA - ca;           // global exclusive A-prefix
        int prefE = prefP0 + xP - cprow;        // global exclusive P-prefix
        int a = KB - pref;
        if (a < 0) a = 0;
        if (a > ca) a = ca;
        shAllowed[lane] = a;
        shPrefE[lane]   = prefE;
        if (pref < KB && pref + ca > KB) {      // partial row lives in MY block
            shProw = blk * 32 + lane;
            shAllowedP = a;
            shPrefP = prefE;
        }
    }
    __syncthreads();

    // rare: this block owns the broad-cutoff partial row -> ordered brute emit
    if (shProw >= 0) {                          // block-uniform branch
        int prow = shProw;
        int allowedP = shAllowedP;
        float2 pp = p2[prow];
        float rp = rad[prow];
        unsigned mA = 0, mP = 0;
        int r0 = t * 4;
        #pragma unroll
        for (int m = 0; m < 4; m++) {
            int j = r0 + m;
            float2 pj = p2[j];
            bool A; bool P;
            pair_flags(pp.x, pp.y, rp, pj.x, pj.y, rad[j], j == prow, A, P);
            mA |= (unsigned)A << m;
            mP |= (unsigned)P << m;
        }
        int baseA = scan1024(__popc(mA), sh32, t);
        unsigned mC = 0;
        #pragma unroll
        for (int m = 0; m < 4; m++) {
            if ((mP >> m) & 1u) {
                int ar = baseA + __popc(mA & ((1u << m) - 1u));
                if (ar < allowedP) mC |= 1u << m;
            }
        }
        int slotBase = shPrefP + scan1024(__popc(mC), sh32, t);
        unsigned mm = mC;
        while (mm) {
            int m = __ffs(mm) - 1;
            mm &= mm - 1;
            int slot = slotBase++;
            if (slot < KE) {
                int j = r0 + m;
                float2 pj = p2[j];
                emit_pair(slot, prow, j, pp.x, pp.y, rp, pj.x, pj.y, rad[j]);
            }
        }
    }

    // ---- P3: warp-parallel RANK-based emit (replaces lane-0 insertion sort;
    //      within-row order = ascending j, so slot = baseE + #{b : j_b < j_a}) --
    {
        int prow = shProw;
        int allowed = shAllowed[wib];
        int baseE = shPrefE[wib];
        bool active = (i != prow) && (allowed != 0) && (baseE < KE) && (cp != 0);
        if (active) {
            // non-partial row with allowed > 0  =>  all P-hits kept
            if (cp <= CAP) {
                for (int a = lane; a < cp; a += 32) {
                    int ja = jls[wib][a];
                    int rank = 0;
                    for (int b = 0; b < cp; b++)
                        rank += (jls[wib][b] < ja);     // broadcast LDS reads
                    int slot = baseE + rank;
                    if (slot < KE) {
                        float xj = pos[2 * ja], yj = pos[2 * ja + 1];
                        emit_pair(slot, i, ja, xi, yi, ri, xj, yj, rad[ja]);
                    }
                }
            } else {
                // rare overflow: warp-strided ordered brute scan
                int rank = 0;
                for (int j0 = 0; j0 < NB; j0 += 32) {
                    int j = j0 + lane;
                    float xj = pos[2 * j], yj = pos[2 * j + 1], rj = rad[j];
                    bool A; bool P;
                    pair_flags(xi, yi, ri, xj, yj, rj, j == i, A, P);
                    unsigned bp = __ballot_sync(FULLM, P);
                    if (P) {
                        int slot = baseE + rank + __popc(bp & ((1u << lane) - 1u));
                        if (slot < KE)
                            emit_pair(slot, i, j, xi, yi, ri, xj, yj, rj);
                    }
                    rank += __popc(bp);
                }
            }
        }
    }
    gsync();

    // ---- P4: re-zero cell histogram + warp-leader resolve ----
    if (t < NCELLS / NBLKS) g_cellCnt[blk * (NCELLS / NBLKS) + t] = 0;
    if (lane == 0) {
        float x = xi, y = yi;
        int w = atomicExch(&g_winner[i], 0);    // read + restore in one op
        if (w > KE) {                            // j-write wins
            int k = w - KE - 1;
            x = __fsub_rn(x, __fmul_rn(0.5f, g_evx[k]));
            y = __fsub_rn(y, __fmul_rn(0.5f, g_evy[k]));
        } else if (w > 0) {                      // i-write wins
            int k = w - 1;
            x = __fadd_rn(x, __fmul_rn(0.5f, g_evx[k]));
            y = __fadd_rn(y, __fmul_rn(0.5f, g_evy[k]));
        }
        out[2 * i]     = x;
        out[2 * i + 1] = y;
    }
}

extern "C" void kernel_launch(void* const* d_in, const int* in_sizes, int n_in,
                              void* d_out, int out_size) {
    const float* pos;
    const float* rad;
    if (in_sizes[0] == 2 * NB) { pos = (const float*)d_in[0]; rad = (const float*)d_in[1]; }
    else                       { pos = (const float*)d_in[1]; rad = (const float*)d_in[0]; }
    float* out = (float*)d_out;

    k_all<<<NBLKS, TPB>>>(pos, rad, out);
}

// round 15
// speedup vs baseline: 1.1179x; 1.0190x over previous
#include <cuda_runtime.h>

// Problem constants (fixed by the reference).
#define NB 4096      // bodies
#define KB 16384     // broad-phase keep count
#define KE 4096      // exact-phase keep count

// Spatial grid: rsum <= 3.0 (radii in [0.5,1.5]); cell 3.25 guarantees any
// AABB-overlapping pair sits in adjacent cells, incl. under edge clamping.
#define NC 128
#define NCELLS (NC * NC)
#define CELL 3.25f
#define ORG  (-208.0f)
#define CAPC 32        // bucket capacity per cell (peak occupancy ~ Poisson(4.4))
#define CAP  64        // per-row gathered list cap (fallback: warp brute scan)
#define FULLM 0xffffffffu

#define NBLKS 128      // 1 block/SM => co-resident; 4096 warps = 1 warp/body
#define TPB   1024
#define NGRP  8        // two-level barrier: 8 groups x 16 blocks

// Winner priority key: monotone with the reference write order
// (all i-phase scatters in slot order, then all j-phase scatters in slot
// order; slot order == lexicographic (i,j) over emitted pairs).
//   key = (phase+1)<<24 | i<<12 | j,   phase: 0=i-write, 1=j-write. 0 = none.
#define KEY_I(i, j) ((1 << 24) | ((i) << 12) | (j))
#define KEY_J(i, j) ((2 << 24) | ((i) << 12) | (j))

// ---- device scratch (no allocations; all state self-restoring across replays) ----
__device__ int    g_cellCnt[NCELLS];          // zero-init; re-zeroed in P4
__device__ float4 g_bucket[NCELLS * CAPC];    // (x, y, r, bitcast(idx))
__device__ int2   g_blkSum[NBLKS];            // per-block (sumA, sumP)
__device__ int    g_winner[NB];               // 0=none; restored by atomicExch in P4

// two-level monotone barrier state (never reset => replay-safe):
// release spin on ONE L2 line (cheap broadcast), arrivals fan over 8 lines.
__device__ int g_grp[NGRP * 32];              // stride 32 ints (no false sharing)
__device__ int g_root;
__device__ int g_gen;

__device__ __forceinline__ void gsync() {
    __syncthreads();
    if (threadIdx.x == 0) {
        int my = *(volatile int*)&g_gen;        // read BEFORE arriving
        __threadfence();
        int v = atomicAdd(&g_grp[(blockIdx.x & (NGRP - 1)) * 32], 1) + 1;
        if ((v & 15) == 0) {                    // 16 blocks per group
            int r = atomicAdd(&g_root, 1) + 1;
            if ((r & (NGRP - 1)) == 0) {
                __threadfence();
                atomicAdd(&g_gen, 1);
            }
        }
        while (*(volatile int*)&g_gen == my) { }
        __threadfence();
    }
    __syncthreads();
}

// Pinned-rounding pair predicate — bit-identical at every use site.
__device__ __forceinline__ void pair_flags(float xi, float yi, float ri,
                                           float xj, float yj, float rj,
                                           bool self, bool& A, bool& P) {
    float dx = fabsf(__fsub_rn(xi, xj));
    float dy = fabsf(__fsub_rn(yi, yj));
    float rs = __fadd_rn(ri, rj);
    A = (dx <= rs) & (dy <= rs) & (!self);
    float d2 = __fadd_rn(__fmaf_rn(dy, dy, __fmul_rn(dx, dx)), 1e-12f);
    P = A & (d2 < __fmul_rn(rs, rs));   // pen>0 <=> rs^2 > d^2+eps (monotone)
}

// Emit = two priority writes; penetration vector is recomputed in resolve.
__device__ __forceinline__ void emit_keys(int i, int j) {
    atomicMax(&g_winner[i], KEY_I(i, j));
    atomicMax(&g_winner[j], KEY_J(i, j));
}

// Block-wide exclusive scan over 1024 ints (only the rare partial-row path).
__device__ __forceinline__ int scan1024(int v, int* sh32, int t) {
    int lane = t & 31, w = t >> 5;
    int x = v;
    #pragma unroll
    for (int d = 1; d < 32; d <<= 1) {
        int y = __shfl_up_sync(FULLM, x, d);
        if (lane >= d) x += y;
    }
    if (lane == 31) sh32[w] = x;
    __syncthreads();
    if (w == 0) {
        int s = sh32[lane];
        int acc = s;
        #pragma unroll
        for (int d = 1; d < 32; d <<= 1) {
            int y = __shfl_up_sync(FULLM, acc, d);
            if (lane >= d) acc += y;
        }
        sh32[lane] = acc - s;
    }
    __syncthreads();
    int r = sh32[w] + x - v;
    __syncthreads();
    return r;
}

// warp-collective neighbor candidate setup: 9 cells around (cx,cy).
__device__ __forceinline__ int nei_setup(int cx, int cy, int lane,
                                         int* st, int* ct, int* ce) {
    int mycell = -1, mycnt = 0;
    if (lane < 9) {
        int x = cx + (lane % 3) - 1;
        int y = cy + (lane / 3) - 1;
        if (x >= 0 && x < NC && y >= 0 && y < NC) {
            mycell = y * NC + x;
            mycnt = min(g_cellCnt[mycell], CAPC);
        }
    }
    int inc = mycnt;
    #pragma unroll
    for (int d = 1; d < 16; d <<= 1) {
        int y = __shfl_up_sync(FULLM, inc, d);
        if (lane >= d) inc += y;
    }
    int total = __shfl_sync(FULLM, inc, 8);
    int myst = inc - mycnt;
    #pragma unroll
    for (int k = 0; k < 9; k++) {
        st[k] = __shfl_sync(FULLM, myst, k);
        ct[k] = __shfl_sync(FULLM, mycnt, k);
        ce[k] = __shfl_sync(FULLM, mycell, k);
    }
    return total;
}
__device__ __forceinline__ int cand_addr(const int* st, const int* ct,
                                         const int* ce, int c) {
    int bcell = 0, boff = 0;
    #pragma unroll
    for (int k = 0; k < 9; k++)
        if (c >= st[k] && c < st[k] + ct[k]) { bcell = ce[k]; boff = c - st[k]; }
    return bcell * CAPC + boff;
}

__global__ void __launch_bounds__(TPB, 1)
k_all(const float* __restrict__ pos, const float* __restrict__ rad,
      float* __restrict__ out) {
    __shared__ int sh32[32];
    __shared__ int shCA[32], shCP[32];          // per-warp row counts
    __shared__ int shAllowed[32], shPrefE[32];
    __shared__ int shProw, shAllowedP, shPrefP;
    __shared__ int sPA[NBLKS], sPP[NBLKS];      // exclusive block prefixes
    __shared__ int jls[32][CAP];                // 8 KB: per-warp P-hit j-lists

    int t    = threadIdx.x;
    int blk  = blockIdx.x;
    int lane = t & 31;
    int wib  = t >> 5;
    int i    = blk * 32 + wib;                  // body owned by this warp
    const float2* p2 = (const float2*)pos;

    // ---- P0: warp-leader inserts own body into its cell bucket ----
    float xi, yi, ri;
    int cellc;
    {
        float px = 0.f, py = 0.f, pr = 0.f;
        int c = 0;
        if (lane == 0) {
            float2 p = p2[i];
            px = p.x; py = p.y; pr = rad[i];
            int cx = (int)floorf((px - ORG) / CELL);
            int cy = (int)floorf((py - ORG) / CELL);
            cx = min(max(cx, 0), NC - 1);
            cy = min(max(cy, 0), NC - 1);
            c = cy * NC + cx;
            int idx = atomicAdd(&g_cellCnt[c], 1);
            if (idx < CAPC)
                g_bucket[c * CAPC + idx] =
                    make_float4(px, py, pr, __int_as_float(i));
        }
        xi    = __shfl_sync(FULLM, px, 0);
        yi    = __shfl_sync(FULLM, py, 0);
        ri    = __shfl_sync(FULLM, pr, 0);
        cellc = __shfl_sync(FULLM, c, 0);
    }
    if (t == 0) { shProw = -1; shAllowedP = 0; }
    gsync();

    // ---- P1: warp-per-body A/P counts + gather P-hit j-list into smem ----
    int cp;                                     // P count (uniform in warp)
    {
        int cx = cellc & (NC - 1), cy = cellc >> 7;
        int st[9], ct[9], ce[9];
        int total = nei_setup(cx, cy, lane, st, ct, ce);
        int ca = 0, k = 0;
        for (int base = 0; base < total; base += 32) {
            int c = base + lane;
            bool A = false, P = false;
            int j = -1;
            if (c < total) {
                float4 b = g_bucket[cand_addr(st, ct, ce, c)];
                j = __float_as_int(b.w);
                pair_flags(xi, yi, ri, b.x, b.y, b.z, j == i, A, P);
            }
            ca += __popc(__ballot_sync(FULLM, A));
            unsigned bp = __ballot_sync(FULLM, P);
            if (P) {
                int slot = k + __popc(bp & ((1u << lane) - 1u));
                if (slot < CAP) jls[wib][slot] = j;
            }
            k += __popc(bp);
        }
        cp = k;
        if (lane == 0) { shCA[wib] = ca; shCP[wib] = cp; }
    }
    __syncthreads();
    if (wib == 0) {                             // publish block sums
        int sa = __reduce_add_sync(FULLM, shCA[lane]);
        int sp = __reduce_add_sync(FULLM, shCP[lane]);
        if (lane == 0) g_blkSum[blk] = make_int2(sa, sp);
    }
    gsync();

    // ---- P2: hierarchical prefix (128 block sums) + cutoff ----
    if (wib == 0) {                             // scan 128 block sums
        int2 v0 = g_blkSum[4 * lane + 0];
        int2 v1 = g_blkSum[4 * lane + 1];
        int2 v2 = g_blkSum[4 * lane + 2];
        int2 v3 = g_blkSum[4 * lane + 3];
        int gA = v0.x + v1.x + v2.x + v3.x;
        int gP = v0.y + v1.y + v2.y + v3.y;
        int xA = gA, xP = gP;
        #pragma unroll
        for (int d = 1; d < 32; d <<= 1) {
            int yA = __shfl_up_sync(FULLM, xA, d);
            int yP = __shfl_up_sync(FULLM, xP, d);
            if (lane >= d) { xA += yA; xP += yP; }
        }
        int baseAex = xA - gA, basePex = xP - gP;
        sPA[4 * lane + 0] = baseAex;
        sPA[4 * lane + 1] = baseAex + v0.x;
        sPA[4 * lane + 2] = baseAex + v0.x + v1.x;
        sPA[4 * lane + 3] = baseAex + v0.x + v1.x + v2.x;
        sPP[4 * lane + 0] = basePex;
        sPP[4 * lane + 1] = basePex + v0.y;
        sPP[4 * lane + 2] = basePex + v0.y + v1.y;
        sPP[4 * lane + 3] = basePex + v0.y + v1.y + v2.y;
    }
    __syncthreads();
    if (wib == 0) {                             // intra-block row prefixes
        int prefA0 = sPA[blk], prefP0 = sPP[blk];
        int ca = shCA[lane], cprow = shCP[lane];
        int xA = ca, xP = cprow;
        #pragma unroll
        for (int d = 1; d < 32; d <<= 1) {
            int yA = __shfl_up_sync(FULLM, xA, d);
            int yP = __shfl_up_sync(FULLM, xP, d);
            if (lane >= d) { xA += yA; xP += yP; }
        }
        int pref  = prefA0 + xA - ca;           // global exclusive A-prefix
        int prefE = prefP0 + xP - cprow;        // global exclusive P-prefix
        int a = KB - pref;
        if (a < 0) a = 0;
        if (a > ca) a = ca;
        shAllowed[lane] = a;
        shPrefE[lane]   = prefE;
        if (pref < KB && pref + ca > KB) {      // partial row lives in MY block
            shProw = blk * 32 + lane;
            shAllowedP = a;
            shPrefP = prefE;
        }
    }
    __syncthreads();

    // rare: this block owns the broad-cutoff partial row -> ordered brute emit
    if (shProw >= 0) {                          // block-uniform branch
        int prow = shProw;
        int allowedP = shAllowedP;
        float2 pp = p2[prow];
        float rp = rad[prow];
        unsigned mA = 0, mP = 0;
        int r0 = t * 4;
        #pragma unroll
        for (int m = 0; m < 4; m++) {
            int j = r0 + m;
            float2 pj = p2[j];
            bool A; bool P;
            pair_flags(pp.x, pp.y, rp, pj.x, pj.y, rad[j], j == prow, A, P);
            mA |= (unsigned)A << m;
            mP |= (unsigned)P << m;
        }
        int baseA = scan1024(__popc(mA), sh32, t);
        unsigned mC = 0;
        #pragma unroll
        for (int m = 0; m < 4; m++) {
            if ((mP >> m) & 1u) {
                int ar = baseA + __popc(mA & ((1u << m) - 1u));
                if (ar < allowedP) mC |= 1u << m;
            }
        }
        int slotBase = shPrefP + scan1024(__popc(mC), sh32, t);
        unsigned mm = mC;
        while (mm) {
            int m = __ffs(mm) - 1;
            mm &= mm - 1;
            int slot = slotBase++;
            if (slot < KE) emit_keys(prow, r0 + m);
        }
    }

    // ---- P3: key-based emit. Rows fully under the KE cutoff emit every hit
    //      with NO rank computation; only the single KE-straddling row ranks. --
    {
        int prow = shProw;
        int allowed = shAllowed[wib];
        int baseE = shPrefE[wib];
        bool active = (i != prow) && (allowed != 0) && (baseE < KE) && (cp != 0);
        if (active) {
            // non-partial row with allowed > 0  =>  all P-hits kept (broad)
            if (cp <= CAP) {
                if (baseE + cp <= KE) {
                    // fast path: every hit survives the exact cutoff
                    for (int a = lane; a < cp; a += 32)
                        emit_keys(i, jls[wib][a]);
                } else {
                    // KE-straddling row (at most one globally): rank by j,
                    // keep only the first (KE - baseE) hits in j order
                    int keep = KE - baseE;
                    for (int a = lane; a < cp; a += 32) {
                        int ja = jls[wib][a];
                        int rank = 0;
                        for (int b = 0; b < cp; b++)
                            rank += (jls[wib][b] < ja);  // broadcast LDS reads
                        if (rank < keep) emit_keys(i, ja);
                    }
                }
            } else {
                // rare overflow: warp-strided ordered brute scan
                int rank = 0;
                for (int j0 = 0; j0 < NB; j0 += 32) {
                    int j = j0 + lane;
                    float xj = pos[2 * j], yj = pos[2 * j + 1], rj = rad[j];
                    bool A; bool P;
                    pair_flags(xi, yi, ri, xj, yj, rj, j == i, A, P);
                    unsigned bp = __ballot_sync(FULLM, P);
                    if (P) {
                        int slot = baseE + rank + __popc(bp & ((1u << lane) - 1u));
                        if (slot < KE) emit_keys(i, j);
                    }
                    rank += __popc(bp);
                }
            }
        }
    }
    gsync();

    // ---- P4: re-zero cell histogram + warp-leader resolve (recompute ev) ----
    if (t < NCELLS / NBLKS) g_cellCnt[blk * (NCELLS / NBLKS) + t] = 0;
    if (lane == 0) {
        float x = xi, y = yi;
        int w = atomicExch(&g_winner[i], 0);    // read + restore in one op
        if (w > 0) {
            int pi = (w >> 12) & 0xFFF;
            int pj = w & 0xFFF;
            float2 a = p2[pi];
            float2 b = p2[pj];
            float rs  = __fadd_rn(rad[pi], rad[pj]);
            float dvx = __fsub_rn(a.x, b.x);
            float dvy = __fsub_rn(a.y, b.y);
            float d2  = __fadd_rn(__fmaf_rn(dvy, dvy, __fmul_rn(dvx, dvx)), 1e-12f);
            float dist = __fsqrt_rn(d2);
            float s = __fdiv_rn(__fsub_rn(rs, dist), dist);   // pen_depth / dist
            float evx = __fmul_rn(dvx, s);
            float evy = __fmul_rn(dvy, s);
            if (w >= (2 << 24)) {                // j-write wins: pos - 0.5*ev
                x = __fsub_rn(x, __fmul_rn(0.5f, evx));
                y = __fsub_rn(y, __fmul_rn(0.5f, evy));
            } else {                             // i-write wins: pos + 0.5*ev
                x = __fadd_rn(x, __fmul_rn(0.5f, evx));
                y = __fadd_rn(y, __fmul_rn(0.5f, evy));
            }
        }
        out[2 * i]     = x;
        out[2 * i + 1] = y;
    }
}

extern "C" void kernel_launch(void* const* d_in, const int* in_sizes, int n_in,
                              void* d_out, int out_size) {
    const float* pos;
    const float* rad;
    if (in_sizes[0] == 2 * NB) { pos = (const float*)d_in[0]; rad = (const float*)d_in[1]; }
    else                       { pos = (const float*)d_in[1]; rad = (const float*)d_in[0]; }
    float* out = (float*)d_out;

    k_all<<<NBLKS, TPB>>>(pos, rad, out);
}